// round 16
// baseline (speedup 1.0000x reference)
#include <cuda_runtime.h>
#include <math.h>

#define BS    32
#define OBJ   128
#define DD    256
#define RR    32
#define EE    64
#define DEPTH 3
#define MTOT  (BS*OBJ)   // 4096

// ---------------- scratch (static device arrays; no allocation) ----------------
__device__ __align__(16) float g_Ao[BS*OBJ*OBJ];      // 2 MB
__device__ __align__(16) float g_Ar[MTOT*RR];         // 0.5MB
__device__ __align__(16) float g_As[MTOT];
__device__ __align__(16) float g_RelW[DEPTH*RR*DD];
__device__ __align__(16) float g_h1[2][MTOT*DD];      // split-K partials of x@(W1+I)[+b1 in part0]
__device__ __align__(16) float g_Xw[2][MTOT*DD];      // split-K partials of x@W2x
__device__ __align__(16) float g_xb0[MTOT*DD];        // ping
__device__ __align__(16) float g_xb1[MTOT*DD];        // pong

// ---------------- f32x2 packed-FMA helpers ----------------
__device__ __forceinline__ unsigned long long pack2(float lo, float hi) {
    unsigned long long r;
    asm("mov.b64 %0, {%1, %2};" : "=l"(r) : "f"(lo), "f"(hi));
    return r;
}
__device__ __forceinline__ float2 unpack2(unsigned long long v) {
    float2 r;
    asm("mov.b64 {%0, %1}, %2;" : "=f"(r.x), "=f"(r.y) : "l"(v));
    return r;
}
__device__ __forceinline__ void ffma2(unsigned long long& c, unsigned long long a, unsigned long long b) {
    asm("fma.rn.f32x2 %0, %1, %2, %0;" : "+l"(c) : "l"(a), "l"(b));
}

// ---------------- pre: A reduction (blocks 0..4095) + RelW (blocks 4096..4191) ----
__global__ __launch_bounds__(256) void pre_kernel(const float* __restrict__ A,
                                                  const float* __restrict__ rel,
                                                  const float* __restrict__ W2) {
    __shared__ float s[OBJ*RR];              // 16 KB
    int bid = blockIdx.x;
    int t = threadIdx.x;
    if (bid < MTOT) {
        const float4* a4 = (const float4*)(A + (size_t)bid * (OBJ*RR));
        float4* s4 = (float4*)s;
#pragma unroll
        for (int i = 0; i < 4; i++) s4[t + i*256] = a4[t + i*256];
        __syncthreads();
        if (t < OBJ) {
            float sum = 0.f;
            int base = t * RR;
#pragma unroll
            for (int j = 0; j < RR; j++) sum += s[base + ((j + t) & 31)];
            g_Ao[(size_t)bid*OBJ + t] = sum;
        } else if (t < OBJ + RR) {           // one full warp
            int j = t - OBJ;
            float sum = 0.f;
#pragma unroll 16
            for (int o = 0; o < OBJ; o++) sum += s[o*RR + j];
            g_Ar[(size_t)bid*RR + j] = sum;
            float tot = sum;
#pragma unroll
            for (int off = 16; off > 0; off >>= 1) tot += __shfl_down_sync(0xffffffffu, tot, off);
            if (j == 0) g_As[bid] = tot;
        }
    } else {
        int p = bid - MTOT;                  // 0..95
        int dep = p >> 5, r = p & 31, f = t;
        const float* w  = W2 + (size_t)dep*(DD+EE)*DD + (size_t)DD*DD + f;
        const float* rr = rel + r*EE;
        float acc = 0.f;
#pragma unroll 8
        for (int e = 0; e < EE; e++) acc += rr[e] * w[(size_t)e*DD];
        g_RelW[(size_t)dep*RR*DD + r*DD + f] = acc;
    }
}

// ---------------- GEMM1 (split-K): [h1|Xw] = x @ [(W1+I) | W2x] --------------
// BM=128, BN=128, BK=16, 256 threads, 8x8/thread via f32x2; grid (4, 32, 2) = 256 blocks
__global__ __launch_bounds__(256, 2) void gemm1_kernel(
    const float* __restrict__ x0, int insel,
    const float* __restrict__ W1, const float* __restrict__ b1,
    const float* __restrict__ W2, int dep)
{
    const float* xin = (insel == 0) ? x0 : ((insel == 1) ? g_xb0 : g_xb1);
    __shared__ __align__(16) float sA[2][16][132];   // k-major
    __shared__ __align__(16) float sB[2][16][128];

    int bx = blockIdx.x, by = blockIdx.y, kz = blockIdx.z;
    int tid = threadIdx.x;
    int tx = tid & 15, ty = tid >> 4;
    int arow = tid >> 2, akv = tid & 3;
    int brow = tid >> 4, bc = (tid & 15) * 8;

    const bool isW1 = (bx < 2);
    const float* Bbase = isW1 ? (W1 + (size_t)dep*DD*DD) : (W2 + (size_t)dep*(DD+EE)*DD);
    const int cb = isW1 ? bx*128 : (bx-2)*128;

    const float* Ablk = xin + (size_t)(by * 128) * DD + kz * 128;
    const float* Bblk = Bbase + (size_t)(kz * 128) * DD + cb;

    unsigned long long c2[4][8];
#pragma unroll
    for (int p = 0; p < 4; p++)
#pragma unroll
        for (int j = 0; j < 8; j++) c2[p][j] = 0ull;

    float4 ra0, ra1, rb0, rb1;
    // ---- load tile 0 ----
    ra0 = *(const float4*)(Ablk + (size_t)arow*DD      + akv*4);
    ra1 = *(const float4*)(Ablk + (size_t)(arow+64)*DD + akv*4);
    rb0 = *(const float4*)(Bblk + (size_t)brow*DD + bc);
    rb1 = *(const float4*)(Bblk + (size_t)brow*DD + bc + 4);
    if (isW1) {                                 // fold residual: W1 + I on the diagonal
        int d = (kz*128 + brow) - (cb + bc);
        if (d >= 0 && d < 4)      (&rb0.x)[d]   += 1.0f;
        else if (d >= 4 && d < 8) (&rb1.x)[d-4] += 1.0f;
    }
    sA[0][akv*4+0][arow]    = ra0.x; sA[0][akv*4+1][arow]    = ra0.y;
    sA[0][akv*4+2][arow]    = ra0.z; sA[0][akv*4+3][arow]    = ra0.w;
    sA[0][akv*4+0][arow+64] = ra1.x; sA[0][akv*4+1][arow+64] = ra1.y;
    sA[0][akv*4+2][arow+64] = ra1.z; sA[0][akv*4+3][arow+64] = ra1.w;
    *(float4*)&sB[0][brow][bc]   = rb0;
    *(float4*)&sB[0][brow][bc+4] = rb1;
    __syncthreads();

    for (int kt = 0; kt < 8; kt++) {
        int s = kt & 1;
        if (kt < 7) {                            // prefetch tile kt+1 into regs
            const float* Ap = Ablk + (kt+1)*16;
            ra0 = *(const float4*)(Ap + (size_t)arow*DD      + akv*4);
            ra1 = *(const float4*)(Ap + (size_t)(arow+64)*DD + akv*4);
            const float* Bp = Bblk + (size_t)((kt+1)*16 + brow)*DD;
            rb0 = *(const float4*)(Bp + bc);
            rb1 = *(const float4*)(Bp + bc + 4);
            if (isW1) {
                int d = (kz*128 + (kt+1)*16 + brow) - (cb + bc);
                if (d >= 0 && d < 4)      (&rb0.x)[d]   += 1.0f;
                else if (d >= 4 && d < 8) (&rb1.x)[d-4] += 1.0f;
            }
        }
#pragma unroll
        for (int k = 0; k < 16; k++) {
            const unsigned long long* ap = (const unsigned long long*)&sA[s][k][ty*8];
            unsigned long long a0 = ap[0], a1 = ap[1], a2v = ap[2], a3v = ap[3];
            const float* bp = &sB[s][k][tx*8];
            float4 bv0 = *(const float4*)bp;
            float4 bv1 = *(const float4*)(bp + 4);
            unsigned long long bd[8];
            bd[0] = pack2(bv0.x, bv0.x); bd[1] = pack2(bv0.y, bv0.y);
            bd[2] = pack2(bv0.z, bv0.z); bd[3] = pack2(bv0.w, bv0.w);
            bd[4] = pack2(bv1.x, bv1.x); bd[5] = pack2(bv1.y, bv1.y);
            bd[6] = pack2(bv1.z, bv1.z); bd[7] = pack2(bv1.w, bv1.w);
#pragma unroll
            for (int j = 0; j < 8; j++) {
                ffma2(c2[0][j], a0,  bd[j]);
                ffma2(c2[1][j], a1,  bd[j]);
                ffma2(c2[2][j], a2v, bd[j]);
                ffma2(c2[3][j], a3v, bd[j]);
            }
        }
        if (kt < 7) {                            // stage tile kt+1 into the other buffer
            int s2 = s ^ 1;
            sA[s2][akv*4+0][arow]    = ra0.x; sA[s2][akv*4+1][arow]    = ra0.y;
            sA[s2][akv*4+2][arow]    = ra0.z; sA[s2][akv*4+3][arow]    = ra0.w;
            sA[s2][akv*4+0][arow+64] = ra1.x; sA[s2][akv*4+1][arow+64] = ra1.y;
            sA[s2][akv*4+2][arow+64] = ra1.z; sA[s2][akv*4+3][arow+64] = ra1.w;
            *(float4*)&sB[s2][brow][bc]   = rb0;
            *(float4*)&sB[s2][brow][bc+4] = rb1;
        }
        __syncthreads();
    }

    // ---- epilogue ----
    int n = cb + tx*8;
    float* dst = isW1 ? g_h1[kz] : g_Xw[kz];
    float4 bias0 = make_float4(0.f,0.f,0.f,0.f), bias1 = bias0;
    if (isW1 && kz == 0) {
        bias0 = *(const float4*)(b1 + dep*DD + n);
        bias1 = *(const float4*)(b1 + dep*DD + n + 4);
    }
#pragma unroll
    for (int p = 0; p < 4; p++) {
        float2 u[8];
#pragma unroll
        for (int j = 0; j < 8; j++) u[j] = unpack2(c2[p][j]);
        int m = by*128 + ty*8 + 2*p;
        *(float4*)&dst[(size_t)m*DD + n]       = make_float4(u[0].x+bias0.x, u[1].x+bias0.y, u[2].x+bias0.z, u[3].x+bias0.w);
        *(float4*)&dst[(size_t)m*DD + n + 4]   = make_float4(u[4].x+bias1.x, u[5].x+bias1.y, u[6].x+bias1.z, u[7].x+bias1.w);
        *(float4*)&dst[(size_t)(m+1)*DD + n]   = make_float4(u[0].y+bias0.x, u[1].y+bias0.y, u[2].y+bias0.z, u[3].y+bias0.w);
        *(float4*)&dst[(size_t)(m+1)*DD + n+4] = make_float4(u[4].y+bias1.x, u[5].y+bias1.y, u[6].y+bias1.z, u[7].y+bias1.w);
    }
}

// ------- combine: out = tanh(h1 + [Ao|Ar]@[Xw|RelW] + As*b2), K=160 ----------
// BM=32, BN=128, BK=16, 256 threads, 4x4/thread; grid (2, 32, 4) = 256 blocks
__global__ __launch_bounds__(256) void combine_kernel(
    int outsel, float* __restrict__ out0, const float* __restrict__ b2v, int dep)
{
    float* xout = (outsel == 0) ? out0 : ((outsel == 1) ? g_xb0 : g_xb1);

    __shared__ __align__(16) float sA[2][16][36];
    __shared__ __align__(16) float sB[2][16][128];

    int bx = blockIdx.x, b = blockIdx.y, mh = blockIdx.z;
    int tid = threadIdx.x;
    int tx = tid & 31, ty = tid >> 5;             // warp-uniform ty -> broadcast a-loads
    int arow = (tid & 127) >> 2, akv = tid & 3;   // tid<128 loads A
    int brow = tid >> 4, bc = (tid & 15) * 8;

    const float* Aob = g_Ao + (size_t)(b*OBJ + mh*32) * OBJ;
    const float* Arb = g_Ar + (size_t)(b*OBJ + mh*32) * RR;
    const float* Xw0 = g_Xw[0] + (size_t)(b*OBJ)*DD + bx*128;
    const float* Xw1 = g_Xw[1] + (size_t)(b*OBJ)*DD + bx*128;
    const float* Rw  = g_RelW + (size_t)dep*RR*DD + bx*128;

    unsigned long long c2[4][2];
#pragma unroll
    for (int m = 0; m < 4; m++) { c2[m][0] = 0ull; c2[m][1] = 0ull; }

    float4 ra, rb0, rb1;
    // ---- load tile 0 (Ao/Xw region) ----
    if (tid < 128) ra = *(const float4*)(Aob + (size_t)arow*OBJ + akv*4);
    {
        float4 t0 = *(const float4*)(Xw0 + (size_t)brow*DD + bc);
        float4 t1 = *(const float4*)(Xw1 + (size_t)brow*DD + bc);
        rb0 = make_float4(t0.x+t1.x, t0.y+t1.y, t0.z+t1.z, t0.w+t1.w);
        float4 s0 = *(const float4*)(Xw0 + (size_t)brow*DD + bc + 4);
        float4 s1 = *(const float4*)(Xw1 + (size_t)brow*DD + bc + 4);
        rb1 = make_float4(s0.x+s1.x, s0.y+s1.y, s0.z+s1.z, s0.w+s1.w);
    }
    if (tid < 128) {
        sA[0][akv*4+0][arow] = ra.x; sA[0][akv*4+1][arow] = ra.y;
        sA[0][akv*4+2][arow] = ra.z; sA[0][akv*4+3][arow] = ra.w;
    }
    *(float4*)&sB[0][brow][bc]   = rb0;
    *(float4*)&sB[0][brow][bc+4] = rb1;
    __syncthreads();

    for (int kt = 0; kt < 10; kt++) {            // K = 160 = 128 (Ao@Xw) + 32 (Ar@RelW)
        int s = kt & 1;
        if (kt < 9) {
            int k0 = (kt+1)*16;
            if (k0 < 128) {
                if (tid < 128) ra = *(const float4*)(Aob + (size_t)arow*OBJ + k0 + akv*4);
                float4 t0 = *(const float4*)(Xw0 + (size_t)(k0+brow)*DD + bc);
                float4 t1 = *(const float4*)(Xw1 + (size_t)(k0+brow)*DD + bc);
                rb0 = make_float4(t0.x+t1.x, t0.y+t1.y, t0.z+t1.z, t0.w+t1.w);
                float4 s0 = *(const float4*)(Xw0 + (size_t)(k0+brow)*DD + bc + 4);
                float4 s1 = *(const float4*)(Xw1 + (size_t)(k0+brow)*DD + bc + 4);
                rb1 = make_float4(s0.x+s1.x, s0.y+s1.y, s0.z+s1.z, s0.w+s1.w);
            } else {
                if (tid < 128) ra = *(const float4*)(Arb + (size_t)arow*RR + (k0-128) + akv*4);
                rb0 = *(const float4*)(Rw + (size_t)(k0-128+brow)*DD + bc);
                rb1 = *(const float4*)(Rw + (size_t)(k0-128+brow)*DD + bc + 4);
            }
        }
#pragma unroll
        for (int k = 0; k < 16; k++) {
            float4 av = *(const float4*)&sA[s][k][ty*4];
            unsigned long long ad0 = pack2(av.x, av.x), ad1 = pack2(av.y, av.y);
            unsigned long long ad2 = pack2(av.z, av.z), ad3 = pack2(av.w, av.w);
            const unsigned long long* bp = (const unsigned long long*)&sB[s][k][tx*4];
            unsigned long long b0 = bp[0], b1v = bp[1];
            ffma2(c2[0][0], ad0, b0); ffma2(c2[0][1], ad0, b1v);
            ffma2(c2[1][0], ad1, b0); ffma2(c2[1][1], ad1, b1v);
            ffma2(c2[2][0], ad2, b0); ffma2(c2[2][1], ad2, b1v);
            ffma2(c2[3][0], ad3, b0); ffma2(c2[3][1], ad3, b1v);
        }
        if (kt < 9) {
            int s2 = s ^ 1;
            if (tid < 128) {
                sA[s2][akv*4+0][arow] = ra.x; sA[s2][akv*4+1][arow] = ra.y;
                sA[s2][akv*4+2][arow] = ra.z; sA[s2][akv*4+3][arow] = ra.w;
            }
            *(float4*)&sB[s2][brow][bc]   = rb0;
            *(float4*)&sB[s2][brow][bc+4] = rb1;
        }
        __syncthreads();
    }

    // ---- epilogue: + (h1a+h1b) + As*b2, tanh (residual folded into W1) ----
    int n = bx*128 + tx*4;
    float4 bv2 = *(const float4*)(b2v + dep*DD + n);
    int rowbase = b*OBJ + mh*32 + ty*4;
#pragma unroll
    for (int m = 0; m < 4; m++) {
        int row = rowbase + m;
        size_t idx = (size_t)row*DD + n;
        float as = g_As[row];
        float4 ha = *(const float4*)&g_h1[0][idx];
        float4 hb = *(const float4*)&g_h1[1][idx];
        float2 p0 = unpack2(c2[m][0]);
        float2 p1 = unpack2(c2[m][1]);
        float4 v;
        v.x = tanhf(p0.x + ha.x + hb.x + as*bv2.x);
        v.y = tanhf(p0.y + ha.y + hb.y + as*bv2.y);
        v.z = tanhf(p1.x + ha.z + hb.z + as*bv2.z);
        v.w = tanhf(p1.y + ha.w + hb.w + as*bv2.w);
        *(float4*)(xout + idx) = v;
    }
}

// ---------------- launch ----------------
extern "C" void kernel_launch(void* const* d_in, const int* in_sizes, int n_in,
                              void* d_out, int out_size) {
    const float* x   = (const float*)d_in[0];
    const float* A   = (const float*)d_in[1];
    const float* rel = (const float*)d_in[2];
    const float* W1  = (const float*)d_in[3];
    const float* b1  = (const float*)d_in[4];
    const float* W2  = (const float*)d_in[5];
    const float* b2  = (const float*)d_in[6];
    float* out = (float*)d_out;

    pre_kernel<<<MTOT + RR*DEPTH, 256>>>(A, rel, W2);

    for (int dep = 0; dep < DEPTH; dep++) {
        int insel  = dep;                              // 0 -> x param, 1 -> g_xb0, 2 -> g_xb1
        int outsel = (dep == DEPTH-1) ? 0 : dep + 1;   // last depth writes d_out
        gemm1_kernel<<<dim3(4, 32, 2), 256>>>(x, insel, W1, b1, W2, dep);
        combine_kernel<<<dim3(2, 32, 4), 256>>>(outsel, out, b2, dep);
    }
}

// round 17
// speedup vs baseline: 1.0013x; 1.0013x over previous
#include <cuda_runtime.h>
#include <math.h>

#define BS    32
#define OBJ   128
#define DD    256
#define RR    32
#define EE    64
#define DEPTH 3
#define MTOT  (BS*OBJ)   // 4096

// ---------------- scratch (static device arrays; no allocation) ----------------
__device__ __align__(16) float g_Ao[BS*OBJ*OBJ];      // 2 MB
__device__ __align__(16) float g_Ar[MTOT*RR];         // 0.5MB
__device__ __align__(16) float g_As[MTOT];
__device__ __align__(16) float g_RelW[DEPTH*RR*DD];
__device__ __align__(16) float g_h1[2][MTOT*DD];      // split-K partials of x@(W1+I)[+b1 in part0]
__device__ __align__(16) float g_Xw[2][MTOT*DD];      // split-K partials of x@W2x
__device__ __align__(16) float g_xb0[MTOT*DD];        // ping
__device__ __align__(16) float g_xb1[MTOT*DD];        // pong

// ---------------- f32x2 packed-FMA helpers ----------------
__device__ __forceinline__ unsigned long long pack2(float lo, float hi) {
    unsigned long long r;
    asm("mov.b64 %0, {%1, %2};" : "=l"(r) : "f"(lo), "f"(hi));
    return r;
}
__device__ __forceinline__ float2 unpack2(unsigned long long v) {
    float2 r;
    asm("mov.b64 {%0, %1}, %2;" : "=f"(r.x), "=f"(r.y) : "l"(v));
    return r;
}
__device__ __forceinline__ void ffma2(unsigned long long& c, unsigned long long a, unsigned long long b) {
    asm("fma.rn.f32x2 %0, %1, %2, %0;" : "+l"(c) : "l"(a), "l"(b));
}

// ---------------- pre: A reduction (blocks 0..4095) + RelW (blocks 4096..4191) ----
__global__ __launch_bounds__(256) void pre_kernel(const float* __restrict__ A,
                                                  const float* __restrict__ rel,
                                                  const float* __restrict__ W2) {
    __shared__ float s[OBJ*RR];              // 16 KB
    int bid = blockIdx.x;
    int t = threadIdx.x;
    if (bid < MTOT) {
        const float4* a4 = (const float4*)(A + (size_t)bid * (OBJ*RR));
        float4* s4 = (float4*)s;
#pragma unroll
        for (int i = 0; i < 4; i++) s4[t + i*256] = a4[t + i*256];
        __syncthreads();
        if (t < OBJ) {
            float sum = 0.f;
            int base = t * RR;
#pragma unroll
            for (int j = 0; j < RR; j++) sum += s[base + ((j + t) & 31)];
            g_Ao[(size_t)bid*OBJ + t] = sum;
        } else if (t < OBJ + RR) {           // one full warp
            int j = t - OBJ;
            float sum = 0.f;
#pragma unroll 16
            for (int o = 0; o < OBJ; o++) sum += s[o*RR + j];
            g_Ar[(size_t)bid*RR + j] = sum;
            float tot = sum;
#pragma unroll
            for (int off = 16; off > 0; off >>= 1) tot += __shfl_down_sync(0xffffffffu, tot, off);
            if (j == 0) g_As[bid] = tot;
        }
    } else {
        int p = bid - MTOT;                  // 0..95
        int dep = p >> 5, r = p & 31, f = t;
        const float* w  = W2 + (size_t)dep*(DD+EE)*DD + (size_t)DD*DD + f;
        const float* rr = rel + r*EE;
        float acc = 0.f;
#pragma unroll 8
        for (int e = 0; e < EE; e++) acc += rr[e] * w[(size_t)e*DD];
        g_RelW[(size_t)dep*RR*DD + r*DD + f] = acc;
    }
}

// ---------------- GEMM1 (split-K): [h1|Xw] = x @ [(W1+I) | W2x] --------------
// BM=128, BN=128, BK=16, 256 threads, 8x8/thread via f32x2; grid (4, 32, 2) = 256 blocks
__global__ __launch_bounds__(256, 2) void gemm1_kernel(
    const float* __restrict__ x0, int insel,
    const float* __restrict__ W1, const float* __restrict__ b1,
    const float* __restrict__ W2, int dep)
{
    const float* xin = (insel == 0) ? x0 : ((insel == 1) ? g_xb0 : g_xb1);
    __shared__ __align__(16) float sA[2][16][132];   // k-major
    __shared__ __align__(16) float sB[2][16][128];

    int bx = blockIdx.x, by = blockIdx.y, kz = blockIdx.z;
    int tid = threadIdx.x;
    int tx = tid & 15, ty = tid >> 4;
    int arow = tid >> 2, akv = tid & 3;
    int brow = tid >> 4, bc = (tid & 15) * 8;

    const bool isW1 = (bx < 2);
    const float* Bbase = isW1 ? (W1 + (size_t)dep*DD*DD) : (W2 + (size_t)dep*(DD+EE)*DD);
    const int cb = isW1 ? bx*128 : (bx-2)*128;

    const float* Ablk = xin + (size_t)(by * 128) * DD + kz * 128;
    const float* Bblk = Bbase + (size_t)(kz * 128) * DD + cb;

    unsigned long long c2[4][8];
#pragma unroll
    for (int p = 0; p < 4; p++)
#pragma unroll
        for (int j = 0; j < 8; j++) c2[p][j] = 0ull;

    float4 ra0, ra1, rb0, rb1;
    // ---- load tile 0 ----
    ra0 = *(const float4*)(Ablk + (size_t)arow*DD      + akv*4);
    ra1 = *(const float4*)(Ablk + (size_t)(arow+64)*DD + akv*4);
    rb0 = *(const float4*)(Bblk + (size_t)brow*DD + bc);
    rb1 = *(const float4*)(Bblk + (size_t)brow*DD + bc + 4);
    if (isW1) {                                 // fold residual: W1 + I on the diagonal
        int d = (kz*128 + brow) - (cb + bc);
        if (d >= 0 && d < 4)      (&rb0.x)[d]   += 1.0f;
        else if (d >= 4 && d < 8) (&rb1.x)[d-4] += 1.0f;
    }
    sA[0][akv*4+0][arow]    = ra0.x; sA[0][akv*4+1][arow]    = ra0.y;
    sA[0][akv*4+2][arow]    = ra0.z; sA[0][akv*4+3][arow]    = ra0.w;
    sA[0][akv*4+0][arow+64] = ra1.x; sA[0][akv*4+1][arow+64] = ra1.y;
    sA[0][akv*4+2][arow+64] = ra1.z; sA[0][akv*4+3][arow+64] = ra1.w;
    *(float4*)&sB[0][brow][bc]   = rb0;
    *(float4*)&sB[0][brow][bc+4] = rb1;
    __syncthreads();

    for (int kt = 0; kt < 8; kt++) {
        int s = kt & 1;
        if (kt < 7) {                            // prefetch tile kt+1 into regs
            const float* Ap = Ablk + (kt+1)*16;
            ra0 = *(const float4*)(Ap + (size_t)arow*DD      + akv*4);
            ra1 = *(const float4*)(Ap + (size_t)(arow+64)*DD + akv*4);
            const float* Bp = Bblk + (size_t)((kt+1)*16 + brow)*DD;
            rb0 = *(const float4*)(Bp + bc);
            rb1 = *(const float4*)(Bp + bc + 4);
            if (isW1) {
                int d = (kz*128 + (kt+1)*16 + brow) - (cb + bc);
                if (d >= 0 && d < 4)      (&rb0.x)[d]   += 1.0f;
                else if (d >= 4 && d < 8) (&rb1.x)[d-4] += 1.0f;
            }
        }
#pragma unroll
        for (int k = 0; k < 16; k++) {
            const unsigned long long* ap = (const unsigned long long*)&sA[s][k][ty*8];
            unsigned long long a0 = ap[0], a1 = ap[1], a2v = ap[2], a3v = ap[3];
            const float* bp = &sB[s][k][tx*8];
            float4 bv0 = *(const float4*)bp;
            float4 bv1 = *(const float4*)(bp + 4);
            unsigned long long bd[8];
            bd[0] = pack2(bv0.x, bv0.x); bd[1] = pack2(bv0.y, bv0.y);
            bd[2] = pack2(bv0.z, bv0.z); bd[3] = pack2(bv0.w, bv0.w);
            bd[4] = pack2(bv1.x, bv1.x); bd[5] = pack2(bv1.y, bv1.y);
            bd[6] = pack2(bv1.z, bv1.z); bd[7] = pack2(bv1.w, bv1.w);
#pragma unroll
            for (int j = 0; j < 8; j++) {
                ffma2(c2[0][j], a0,  bd[j]);
                ffma2(c2[1][j], a1,  bd[j]);
                ffma2(c2[2][j], a2v, bd[j]);
                ffma2(c2[3][j], a3v, bd[j]);
            }
        }
        if (kt < 7) {                            // stage tile kt+1 into the other buffer
            int s2 = s ^ 1;
            sA[s2][akv*4+0][arow]    = ra0.x; sA[s2][akv*4+1][arow]    = ra0.y;
            sA[s2][akv*4+2][arow]    = ra0.z; sA[s2][akv*4+3][arow]    = ra0.w;
            sA[s2][akv*4+0][arow+64] = ra1.x; sA[s2][akv*4+1][arow+64] = ra1.y;
            sA[s2][akv*4+2][arow+64] = ra1.z; sA[s2][akv*4+3][arow+64] = ra1.w;
            *(float4*)&sB[s2][brow][bc]   = rb0;
            *(float4*)&sB[s2][brow][bc+4] = rb1;
        }
        __syncthreads();
    }

    // ---- epilogue ----
    int n = cb + tx*8;
    float* dst = isW1 ? g_h1[kz] : g_Xw[kz];
    float4 bias0 = make_float4(0.f,0.f,0.f,0.f), bias1 = bias0;
    if (isW1 && kz == 0) {
        bias0 = *(const float4*)(b1 + dep*DD + n);
        bias1 = *(const float4*)(b1 + dep*DD + n + 4);
    }
#pragma unroll
    for (int p = 0; p < 4; p++) {
        float2 u[8];
#pragma unroll
        for (int j = 0; j < 8; j++) u[j] = unpack2(c2[p][j]);
        int m = by*128 + ty*8 + 2*p;
        *(float4*)&dst[(size_t)m*DD + n]       = make_float4(u[0].x+bias0.x, u[1].x+bias0.y, u[2].x+bias0.z, u[3].x+bias0.w);
        *(float4*)&dst[(size_t)m*DD + n + 4]   = make_float4(u[4].x+bias1.x, u[5].x+bias1.y, u[6].x+bias1.z, u[7].x+bias1.w);
        *(float4*)&dst[(size_t)(m+1)*DD + n]   = make_float4(u[0].y+bias0.x, u[1].y+bias0.y, u[2].y+bias0.z, u[3].y+bias0.w);
        *(float4*)&dst[(size_t)(m+1)*DD + n+4] = make_float4(u[4].y+bias1.x, u[5].y+bias1.y, u[6].y+bias1.z, u[7].y+bias1.w);
    }
}

// ------- combine: out = tanh(h1 + [Ao|Ar]@[Xw|RelW] + As*b2), K=160 ----------
// BM=32, BN=128, BK=16, 256 threads, 4x4/thread; grid (2, 32, 4) = 256 blocks
__global__ __launch_bounds__(256) void combine_kernel(
    int outsel, float* __restrict__ out0, const float* __restrict__ b2v, int dep)
{
    float* xout = (outsel == 0) ? out0 : ((outsel == 1) ? g_xb0 : g_xb1);

    __shared__ __align__(16) float sA[2][16][36];
    __shared__ __align__(16) float sB[2][16][128];

    int bx = blockIdx.x, b = blockIdx.y, mh = blockIdx.z;
    int tid = threadIdx.x;
    int tx = tid & 31, ty = tid >> 5;             // warp-uniform ty -> broadcast a-loads
    int arow = (tid & 127) >> 2, akv = tid & 3;   // tid<128 loads A
    int brow = tid >> 4, bc = (tid & 15) * 8;

    const float* Aob = g_Ao + (size_t)(b*OBJ + mh*32) * OBJ;
    const float* Arb = g_Ar + (size_t)(b*OBJ + mh*32) * RR;
    const float* Xw0 = g_Xw[0] + (size_t)(b*OBJ)*DD + bx*128;
    const float* Xw1 = g_Xw[1] + (size_t)(b*OBJ)*DD + bx*128;
    const float* Rw  = g_RelW + (size_t)dep*RR*DD + bx*128;

    unsigned long long c2[4][2];
#pragma unroll
    for (int m = 0; m < 4; m++) { c2[m][0] = 0ull; c2[m][1] = 0ull; }

    float4 ra, rb0, rb1;
    // ---- load tile 0 (Ao/Xw region) ----
    if (tid < 128) ra = *(const float4*)(Aob + (size_t)arow*OBJ + akv*4);
    {
        float4 t0 = *(const float4*)(Xw0 + (size_t)brow*DD + bc);
        float4 t1 = *(const float4*)(Xw1 + (size_t)brow*DD + bc);
        rb0 = make_float4(t0.x+t1.x, t0.y+t1.y, t0.z+t1.z, t0.w+t1.w);
        float4 s0 = *(const float4*)(Xw0 + (size_t)brow*DD + bc + 4);
        float4 s1 = *(const float4*)(Xw1 + (size_t)brow*DD + bc + 4);
        rb1 = make_float4(s0.x+s1.x, s0.y+s1.y, s0.z+s1.z, s0.w+s1.w);
    }
    if (tid < 128) {
        sA[0][akv*4+0][arow] = ra.x; sA[0][akv*4+1][arow] = ra.y;
        sA[0][akv*4+2][arow] = ra.z; sA[0][akv*4+3][arow] = ra.w;
    }
    *(float4*)&sB[0][brow][bc]   = rb0;
    *(float4*)&sB[0][brow][bc+4] = rb1;
    __syncthreads();

    for (int kt = 0; kt < 10; kt++) {            // K = 160 = 128 (Ao@Xw) + 32 (Ar@RelW)
        int s = kt & 1;
        if (kt < 9) {
            int k0 = (kt+1)*16;
            if (k0 < 128) {
                if (tid < 128) ra = *(const float4*)(Aob + (size_t)arow*OBJ + k0 + akv*4);
                float4 t0 = *(const float4*)(Xw0 + (size_t)(k0+brow)*DD + bc);
                float4 t1 = *(const float4*)(Xw1 + (size_t)(k0+brow)*DD + bc);
                rb0 = make_float4(t0.x+t1.x, t0.y+t1.y, t0.z+t1.z, t0.w+t1.w);
                float4 s0 = *(const float4*)(Xw0 + (size_t)(k0+brow)*DD + bc + 4);
                float4 s1 = *(const float4*)(Xw1 + (size_t)(k0+brow)*DD + bc + 4);
                rb1 = make_float4(s0.x+s1.x, s0.y+s1.y, s0.z+s1.z, s0.w+s1.w);
            } else {
                if (tid < 128) ra = *(const float4*)(Arb + (size_t)arow*RR + (k0-128) + akv*4);
                rb0 = *(const float4*)(Rw + (size_t)(k0-128+brow)*DD + bc);
                rb1 = *(const float4*)(Rw + (size_t)(k0-128+brow)*DD + bc + 4);
            }
        }
#pragma unroll
        for (int k = 0; k < 16; k++) {
            float4 av = *(const float4*)&sA[s][k][ty*4];
            unsigned long long ad0 = pack2(av.x, av.x), ad1 = pack2(av.y, av.y);
            unsigned long long ad2 = pack2(av.z, av.z), ad3 = pack2(av.w, av.w);
            const unsigned long long* bp = (const unsigned long long*)&sB[s][k][tx*4];
            unsigned long long b0 = bp[0], b1v = bp[1];
            ffma2(c2[0][0], ad0, b0); ffma2(c2[0][1], ad0, b1v);
            ffma2(c2[1][0], ad1, b0); ffma2(c2[1][1], ad1, b1v);
            ffma2(c2[2][0], ad2, b0); ffma2(c2[2][1], ad2, b1v);
            ffma2(c2[3][0], ad3, b0); ffma2(c2[3][1], ad3, b1v);
        }
        if (kt < 9) {
            int s2 = s ^ 1;
            if (tid < 128) {
                sA[s2][akv*4+0][arow] = ra.x; sA[s2][akv*4+1][arow] = ra.y;
                sA[s2][akv*4+2][arow] = ra.z; sA[s2][akv*4+3][arow] = ra.w;
            }
            *(float4*)&sB[s2][brow][bc]   = rb0;
            *(float4*)&sB[s2][brow][bc+4] = rb1;
        }
        __syncthreads();
    }

    // ---- epilogue: + (h1a+h1b) + As*b2, tanh (residual folded into W1) ----
    int n = bx*128 + tx*4;
    float4 bv2 = *(const float4*)(b2v + dep*DD + n);
    int rowbase = b*OBJ + mh*32 + ty*4;
#pragma unroll
    for (int m = 0; m < 4; m++) {
        int row = rowbase + m;
        size_t idx = (size_t)row*DD + n;
        float as = g_As[row];
        float4 ha = *(const float4*)&g_h1[0][idx];
        float4 hb = *(const float4*)&g_h1[1][idx];
        float2 p0 = unpack2(c2[m][0]);
        float2 p1 = unpack2(c2[m][1]);
        float4 v;
        v.x = tanhf(p0.x + ha.x + hb.x + as*bv2.x);
        v.y = tanhf(p0.y + ha.y + hb.y + as*bv2.y);
        v.z = tanhf(p1.x + ha.z + hb.z + as*bv2.z);
        v.w = tanhf(p1.y + ha.w + hb.w + as*bv2.w);
        *(float4*)(xout + idx) = v;
    }
}

// ---------------- launch ----------------
extern "C" void kernel_launch(void* const* d_in, const int* in_sizes, int n_in,
                              void* d_out, int out_size) {
    const float* x   = (const float*)d_in[0];
    const float* A   = (const float*)d_in[1];
    const float* rel = (const float*)d_in[2];
    const float* W1  = (const float*)d_in[3];
    const float* b1  = (const float*)d_in[4];
    const float* W2  = (const float*)d_in[5];
    const float* b2  = (const float*)d_in[6];
    float* out = (float*)d_out;

    pre_kernel<<<MTOT + RR*DEPTH, 256>>>(A, rel, W2);

    for (int dep = 0; dep < DEPTH; dep++) {
        int insel  = dep;                              // 0 -> x param, 1 -> g_xb0, 2 -> g_xb1
        int outsel = (dep == DEPTH-1) ? 0 : dep + 1;   // last depth writes d_out
        gemm1_kernel<<<dim3(4, 32, 2), 256>>>(x, insel, W1, b1, W2, dep);
        combine_kernel<<<dim3(2, 32, 4), 256>>>(outsel, out, b2, dep);
    }
}